// round 17
// baseline (speedup 1.0000x reference)
#include <cuda_runtime.h>
#include <cuda_fp16.h>
#include <cstdint>

// TM-CFAR: out = rd_map / trimmed_mean(sorted 126 reference cells, ranks [31,94))
// Window 9x15, guard 3x3, zero padding.
//
// Round-17: 64x8 patch; OCTET shared-window histogram (8 pixels per histogram).
//  - u64 bins: byte p = count for pixel p of the octet (counts <= 126)
//  - 9x22 = 198 union cells, ONE u64 atomic per cell, guard folded into mask
//  - lo/hi u32 halves scanned independently (byte cums <= 126: carry-free)
//  - epilogue per quad (2 per octet), unchanged bit-exact semantics
//  - clean octets: 256-wide bucket direct (midpoint +-128); padding-affected
//    octets: 8 exact bisection steps inside bucket

#define TILE_WQ   80      // qword tile stride (u64 units) == pair stride
#define TILE_ROWS 16
#define KBIAS     1024
#define KSCALE    30720.0f
#define SENT2     0x7BFF7BFFu   // max-finite fp16: never below any threshold, hmul-safe

static __device__ __forceinline__ unsigned h2u(__half2 h) { return *reinterpret_cast<unsigned*>(&h); }
static __device__ __forceinline__ __half2  u2h(unsigned u) { return *reinterpret_cast<__half2*>(&u); }

// STARTBIT < STOPBIT => zero bisection steps, epilogue only, MIDOFF = 1<<(STOPBIT-1)
template <int STARTBIT, int STOPBIT>
static __device__ __forceinline__ void bisect_pair(
    unsigned pk0, unsigned pk1, unsigned pk2, unsigned pk3,
    unsigned A2, unsigned B2,
    float& scP, float& scQ)
{
    const __half2 magic = u2h(0x64006400u);   // (1024.0, 1024.0)

    #pragma unroll
    for (int bit = STARTBIT; bit >= STOPBIT; --bit) {
        const unsigned step2 = (1u << bit) * 0x10001u;
        const __half2 mA = u2h(A2 + step2);
        const __half2 mB = u2h(B2 + step2);

        __half2 sA = __hadd2(__hadd2(__hlt2(u2h(pk0), mA), __hlt2(u2h(pk1), mA)),
                             __hadd2(__hlt2(u2h(pk2), mA), __hlt2(u2h(pk3), mA)));
        __half2 sB = __hadd2(__hadd2(__hlt2(u2h(pk0), mB), __hlt2(u2h(pk1), mB)),
                             __hadd2(__hlt2(u2h(pk2), mB), __hlt2(u2h(pk3), mB)));
        const unsigned Ar = h2u(__hadd2(sA, magic));   // bytes (cAP, 0x64, cAQ, 0x64)
        const unsigned Br = h2u(__hadd2(sB, magic));
        unsigned cc = __byte_perm(Ar, Br, 0x6420);     // (cAP, cAQ, cBP, cBQ)
        cc = __reduce_add_sync(0xffffffffu, cc);

        // byte-wise accept flags: bytes 0,1 vs 30 ; bytes 2,3 vs 94
        const unsigned f = ((0xDEDE9E9Eu - cc) >> 7) & 0x01010101u;
        A2 += __byte_perm(f, 0, 0x4140) << bit;   // (fAP | fAQ<<16) << bit
        B2 += __byte_perm(f, 0, 0x4342) << bit;
    }

    const int MIDOFF = (STOPBIT > 0) ? (1 << (STOPBIT - 1)) : 0;

    // ---- epilogue: exact counts below brackets + masked range sums ----
    const __half2 hA = u2h(A2), hB = u2h(B2);
    const __half2 lA0 = __hlt2(u2h(pk0), hA), lA1 = __hlt2(u2h(pk1), hA);
    const __half2 lA2v = __hlt2(u2h(pk2), hA), lA3 = __hlt2(u2h(pk3), hA);
    const __half2 lB0 = __hlt2(u2h(pk0), hB), lB1 = __hlt2(u2h(pk1), hB);
    const __half2 lB2v = __hlt2(u2h(pk2), hB), lB3 = __hlt2(u2h(pk3), hB);

    const unsigned in0 = h2u(lB0) & ~h2u(lA0);
    const unsigned in1 = h2u(lB1) & ~h2u(lA1);
    const unsigned in2 = h2u(lB2v) & ~h2u(lA2v);
    const unsigned in3 = h2u(lB3) & ~h2u(lA3);

    const unsigned km0 = h2u(__hmul2(u2h(pk0), u2h(in0)));
    const unsigned km1 = h2u(__hmul2(u2h(pk1), u2h(in1)));
    const unsigned km2 = h2u(__hmul2(u2h(pk2), u2h(in2)));
    const unsigned km3 = h2u(__hmul2(u2h(pk3), u2h(in3)));

    // halfword-pair pack + SIMD add (lanes <= 2*31743, no carry)
    const unsigned lo01 = __byte_perm(km0, km1, 0x5410);
    const unsigned lo23 = __byte_perm(km2, km3, 0x5410);
    const unsigned hi01 = __byte_perm(km0, km1, 0x7632);
    const unsigned hi23 = __byte_perm(km2, km3, 0x7632);
    const unsigned vlo = __vadd2(lo01, lo23);
    const unsigned vhi = __vadd2(hi01, hi23);
    unsigned sP = (vlo & 0xFFFFu) + (vlo >> 16);
    unsigned sQ = (vhi & 0xFFFFu) + (vhi >> 16);

    const __half2 cA2 = __hadd2(__hadd2(lA0, lA1), __hadd2(lA2v, lA3));
    const __half2 cB2 = __hadd2(__hadd2(lB0, lB1), __hadd2(lB2v, lB3));
    unsigned ccf = __byte_perm(h2u(__hadd2(cA2, magic)), h2u(__hadd2(cB2, magic)), 0x6420);

    ccf = __reduce_add_sync(0xffffffffu, ccf);
    sP  = __reduce_add_sync(0xffffffffu, sP);
    sQ  = __reduce_add_sync(0xffffffffu, sQ);

    const int cAP = (int)(ccf & 255u);
    const int cAQ = (int)((ccf >> 8) & 255u);
    const int cBP = (int)((ccf >> 16) & 255u);
    const int cBQ = (int)(ccf >> 24);

    const int TAP = (int)(A2 & 0xFFFFu) + MIDOFF, TAQ = (int)(A2 >> 16) + MIDOFF;
    const int TBP = (int)(B2 & 0xFFFFu) + MIDOFF, TBQ = (int)(B2 >> 16) + MIDOFF;

    const int keptP = (int)sP - KBIAS * (cBP - cAP)
                    + (94 - cBP) * (TBP - KBIAS) - (31 - cAP) * (TAP - KBIAS);
    const int keptQ = (int)sQ - KBIAS * (cBQ - cAQ)
                    + (94 - cBQ) * (TBQ - KBIAS) - (31 - cAQ) * (TAQ - KBIAS);

    scP = __fdividef(63.0f * KSCALE, (float)keptP);
    scQ = __fdividef(63.0f * KSCALE, (float)keptQ);
}

__global__ __launch_bounds__(256, 5)
void tmcfar_kernel(const float* __restrict__ in, float* __restrict__ out,
                   int H, int W)
{
    __shared__ unsigned pairs[TILE_ROWS * TILE_WQ];            // 5120 B (build only)
    __shared__ unsigned long long qtile[TILE_ROWS * TILE_WQ];  // 10240 B
    __shared__ int            offs[128];                       // qword-unit offsets
    __shared__ unsigned long long maskTbl[224];                // u64 mask per cell slot
    __shared__ unsigned short idxTbl[224];                     // u16-unit cell index
    __shared__ __align__(16) unsigned long long hist[8][128];  // byte p = pixel p count

    const int tid  = threadIdx.x;
    const int lane = tid & 31;
    const int wrp  = tid >> 5;
    const int bz   = blockIdx.z;
    const int py0  = blockIdx.y * 8;
    const int px0  = blockIdx.x * 64;

    // compacted (dy,dx) offsets of the 126 reference cells (qword units)
    if (tid < 135) {
        int r = tid / 15, c = tid - r * 15;
        bool guard = (r >= 3 && r <= 5 && c >= 6 && c <= 8);
        if (!guard) {
            int rowsBefore = min(max(r - 3, 0), 3);
            int sameRow    = (r >= 3 && r <= 5) ? min(max(c - 6, 0), 3) : 0;
            int gb = 3 * rowsBefore + sameRow;
            offs[tid - gb] = (r - 4) * TILE_WQ + (c - 7);
        }
    }

    // octet slot tables: cell n = tid over 9 rows x 22 union cols (198 cells)
    // byte p of mask = 1 if cell in pixel-p window [p, p+14] minus guard
    if (tid < 224) {
        unsigned long long m = 0;
        unsigned short idx = 0;
        if (tid < 198) {
            const int r = tid / 22, u = tid - r * 22;
            const bool grow = (r >= 3 && r <= 5);
            #pragma unroll
            for (int pp = 0; pp < 8; ++pp) {
                const bool inw = (u >= pp) && (u <= pp + 14);
                const bool ing = grow && (u >= pp + 6) && (u <= pp + 8);
                if (inw && !ing) m |= (1ULL << (8 * pp));
            }
            idx = (unsigned short)((r * TILE_WQ + u) * 4);  // u16 units, warp-relative
        }
        maskTbl[tid] = m;
        idxTbl[tid]  = idx;
    }

    // ---- phase 1: pair tile (2D mapping) ----
    const int gy0 = py0 - 4, gx0 = px0 - 7;
    const float* inb = in + (size_t)bz * H * W;
    {
        const int trow = tid >> 4;      // 0..15
        const int tcol = tid & 15;      // 0..15
        const int gy = gy0 + trow;
        const bool okr = (gy >= 0) & (gy < H);
        const float* rowp = inb + gy * W;
        #pragma unroll
        for (int k = 0; k < 5; ++k) {
            const int c = tcol + 16 * k;
            const int gx = gx0 + c;
            float v0 = (okr && gx >= 0     && gx < W)     ? rowp[gx]     : 0.0f;
            float v1 = (okr && gx + 1 >= 0 && gx + 1 < W) ? rowp[gx + 1] : 0.0f;
            unsigned k0 = min((unsigned)(v0 * KSCALE), 30719u) + (unsigned)KBIAS;
            unsigned k1 = min((unsigned)(v1 * KSCALE), 30719u) + (unsigned)KBIAS;
            pairs[trow * TILE_WQ + c] = k0 | (k1 << 16);
        }
    }
    __syncthreads();

    // ---- phase 2: qword tile, entry c = k[c..c+3], built through c=77 ----
    {
        const int trow = tid >> 4;
        const int tcol = tid & 15;
        #pragma unroll
        for (int k = 0; k < 5; ++k) {
            const int c = tcol + 16 * k;
            if (c <= 77) {
                qtile[trow * TILE_WQ + c] =
                    (unsigned long long)pairs[trow * TILE_WQ + c]
                  | ((unsigned long long)pairs[trow * TILE_WQ + c + 2] << 32);
            }
        }
    }
    __syncthreads();

    const int py = py0 + wrp;
    const bool exY = (py < 4) | (py >= H - 4);   // warp-uniform

    const int o0 = offs[lane];
    const int o1 = offs[lane + 32];
    const int o2 = offs[lane + 64];
    const int o3 = (lane < 30) ? offs[lane + 96] : 0;
    const bool has3 = (lane < 30);

    const unsigned short* qsW = (const unsigned short*)qtile + wrp * TILE_WQ * 4;
    const unsigned long long* qrow = &qtile[(wrp + 4) * TILE_WQ + 7];
    unsigned long long* hf = &hist[wrp][0];
    float ms0 = 0.0f, ms1 = 0.0f;   // pixels (px0+lane) and (px0+lane+32)

    #pragma unroll 1
    for (int o = 0; o < 8; ++o) {
        // ---- octet histogram: <=7 u64 atomics per lane ----
        {
            ulonglong2 z; z.x = 0; z.y = 0;
            reinterpret_cast<ulonglong2*>(&hf[lane * 4])[0] = z;
            reinterpret_cast<ulonglong2*>(&hf[lane * 4])[1] = z;
        }
        __syncwarp();
        const int sh = 32 * o;   // octet slides 8 cols = 32 u16
        #pragma unroll
        for (int j = 0; j < 6; ++j) {
            const unsigned k = qsW[idxTbl[j * 32 + lane] + sh];
            atomicAdd(&hf[k >> 8], maskTbl[j * 32 + lane]);
        }
        if (lane < 6) {
            const unsigned k = qsW[idxTbl[192 + lane] + sh];
            atomicAdd(&hf[k >> 8], maskTbl[192 + lane]);
        }
        __syncwarp();

        // ---- load 4 u64 bins; lo/hi halves independent (byte cums <= 126) ----
        const ulonglong2 c01 = reinterpret_cast<const ulonglong2*>(&hf[lane * 4])[0];
        const ulonglong2 c23 = reinterpret_cast<const ulonglong2*>(&hf[lane * 4])[1];
        unsigned qlo0 = (unsigned)c01.x,            qhi0 = (unsigned)(c01.x >> 32);
        unsigned qlo1 = qlo0 + (unsigned)c01.y,     qhi1 = qhi0 + (unsigned)(c01.y >> 32);
        unsigned qlo2 = qlo1 + (unsigned)c23.x,     qhi2 = qhi1 + (unsigned)(c23.x >> 32);
        unsigned qlo3 = qlo2 + (unsigned)c23.y,     qhi3 = qhi2 + (unsigned)(c23.y >> 32);
        unsigned inclL = qlo3, inclH = qhi3;
        #pragma unroll
        for (int d = 1; d < 32; d <<= 1) {
            unsigned tL = __shfl_up_sync(0xffffffffu, inclL, d);
            unsigned tH = __shfl_up_sync(0xffffffffu, inclH, d);
            if (lane >= d) { inclL += tL; inclH += tH; }
        }
        const unsigned exL = inclL - qlo3, exH = inclH - qhi3;
        qlo0 += exL; qlo1 += exL; qlo2 += exL; qlo3 += exL;
        qhi0 += exH; qhi1 += exH; qhi2 += exH; qhi3 += exH;

        // ---- byte-SIMD bucket search: 4 REDUX for all 8 pixels ----
        const unsigned g30L = (((0x9E9E9E9Eu - qlo0) >> 7) & 0x01010101u)
                            + (((0x9E9E9E9Eu - qlo1) >> 7) & 0x01010101u)
                            + (((0x9E9E9E9Eu - qlo2) >> 7) & 0x01010101u)
                            + (((0x9E9E9E9Eu - qlo3) >> 7) & 0x01010101u);
        const unsigned g94L = (((0xDEDEDEDEu - qlo0) >> 7) & 0x01010101u)
                            + (((0xDEDEDEDEu - qlo1) >> 7) & 0x01010101u)
                            + (((0xDEDEDEDEu - qlo2) >> 7) & 0x01010101u)
                            + (((0xDEDEDEDEu - qlo3) >> 7) & 0x01010101u);
        const unsigned g30H = (((0x9E9E9E9Eu - qhi0) >> 7) & 0x01010101u)
                            + (((0x9E9E9E9Eu - qhi1) >> 7) & 0x01010101u)
                            + (((0x9E9E9E9Eu - qhi2) >> 7) & 0x01010101u)
                            + (((0x9E9E9E9Eu - qhi3) >> 7) & 0x01010101u);
        const unsigned g94H = (((0xDEDEDEDEu - qhi0) >> 7) & 0x01010101u)
                            + (((0xDEDEDEDEu - qhi1) >> 7) & 0x01010101u)
                            + (((0xDEDEDEDEu - qhi2) >> 7) & 0x01010101u)
                            + (((0xDEDEDEDEu - qhi3) >> 7) & 0x01010101u);
        const unsigned w30L = __reduce_add_sync(0xffffffffu, g30L);  // buckets px 0..3
        const unsigned w94L = __reduce_add_sync(0xffffffffu, g94L);
        const unsigned w30H = __reduce_add_sync(0xffffffffu, g30H);  // buckets px 4..7
        const unsigned w94H = __reduce_add_sync(0xffffffffu, g94H);

        const int pxO = px0 + 8 * o;
        const bool exact = exY | (pxO < 7) | (pxO + 7 >= W - 7);

        // ---- quad A: octet pixels 0..3 ----
        {
            const unsigned long long* p = qrow + 8 * o;
            const unsigned long long w0 = p[o0];
            const unsigned long long w1 = p[o1];
            const unsigned long long w2 = p[o2];
            const unsigned long long w3 = p[o3];
            const unsigned a0 = (unsigned)w0, b0 = (unsigned)(w0 >> 32);
            const unsigned a1 = (unsigned)w1, b1 = (unsigned)(w1 >> 32);
            const unsigned a2 = (unsigned)w2, b2 = (unsigned)(w2 >> 32);
            const unsigned a3 = has3 ? (unsigned)w3 : SENT2;
            const unsigned b3 = has3 ? (unsigned)(w3 >> 32) : SENT2;

            const unsigned A2pq = __byte_perm(w30L, 0, 0x1404);
            const unsigned B2pq = __byte_perm(w94L, 0, 0x1404);
            const unsigned A2rs = __byte_perm(w30L, 0, 0x3424);
            const unsigned B2rs = __byte_perm(w94L, 0, 0x3424);

            float s0, s1, s2, s3;
            if (exact) {
                bisect_pair<7, 0>(a0, a1, a2, a3, A2pq, B2pq, s0, s1);
                bisect_pair<7, 0>(b0, b1, b2, b3, A2rs, B2rs, s2, s3);
            } else {
                bisect_pair<7, 8>(a0, a1, a2, a3, A2pq, B2pq, s0, s1);
                bisect_pair<7, 8>(b0, b1, b2, b3, A2rs, B2rs, s2, s3);
            }
            const int base = 8 * o;      // local pixel of s0
            if (o < 4) {
                if (lane == base)     ms0 = s0;
                if (lane == base + 1) ms0 = s1;
                if (lane == base + 2) ms0 = s2;
                if (lane == base + 3) ms0 = s3;
            } else {
                const int t = base - 32;
                if (lane == t)     ms1 = s0;
                if (lane == t + 1) ms1 = s1;
                if (lane == t + 2) ms1 = s2;
                if (lane == t + 3) ms1 = s3;
            }
        }
        // ---- quad B: octet pixels 4..7 ----
        {
            const unsigned long long* p = qrow + 8 * o + 4;
            const unsigned long long w0 = p[o0];
            const unsigned long long w1 = p[o1];
            const unsigned long long w2 = p[o2];
            const unsigned long long w3 = p[o3];
            const unsigned a0 = (unsigned)w0, b0 = (unsigned)(w0 >> 32);
            const unsigned a1 = (unsigned)w1, b1 = (unsigned)(w1 >> 32);
            const unsigned a2 = (unsigned)w2, b2 = (unsigned)(w2 >> 32);
            const unsigned a3 = has3 ? (unsigned)w3 : SENT2;
            const unsigned b3 = has3 ? (unsigned)(w3 >> 32) : SENT2;

            const unsigned A2pq = __byte_perm(w30H, 0, 0x1404);
            const unsigned B2pq = __byte_perm(w94H, 0, 0x1404);
            const unsigned A2rs = __byte_perm(w30H, 0, 0x3424);
            const unsigned B2rs = __byte_perm(w94H, 0, 0x3424);

            float s0, s1, s2, s3;
            if (exact) {
                bisect_pair<7, 0>(a0, a1, a2, a3, A2pq, B2pq, s0, s1);
                bisect_pair<7, 0>(b0, b1, b2, b3, A2rs, B2rs, s2, s3);
            } else {
                bisect_pair<7, 8>(a0, a1, a2, a3, A2pq, B2pq, s0, s1);
                bisect_pair<7, 8>(b0, b1, b2, b3, A2rs, B2rs, s2, s3);
            }
            const int base = 8 * o + 4;
            if (o < 4) {
                if (lane == base)     ms0 = s0;
                if (lane == base + 1) ms0 = s1;
                if (lane == base + 2) ms0 = s2;
                if (lane == base + 3) ms0 = s3;
            } else {
                const int t = base - 32;
                if (lane == t)     ms1 = s0;
                if (lane == t + 1) ms1 = s1;
                if (lane == t + 2) ms1 = s2;
                if (lane == t + 3) ms1 = s3;
            }
        }
    }

    const size_t rowbase = (size_t)bz * H * W + (size_t)py * W + px0;
    out[rowbase + lane]      = inb[py * W + px0 + lane]      * ms0;
    out[rowbase + lane + 32] = inb[py * W + px0 + lane + 32] * ms1;
}

extern "C" void kernel_launch(void* const* d_in, const int* in_sizes, int n_in,
                              void* d_out, int out_size)
{
    const float* in = (const float*)d_in[0];
    float* out = (float*)d_out;
    const int H = 512, W = 512;
    const int B = in_sizes[0] / (H * W);

    dim3 grid(W / 64, H / 8, B);
    dim3 block(256);
    tmcfar_kernel<<<grid, block>>>(in, out, H, W);
}